// round 15
// baseline (speedup 1.0000x reference)
#include <cuda_runtime.h>
#include <cuda_bf16.h>
#include <cstdint>

// TopKRoute: y = x.reshape(64, 786432) @ W^T + b ; scatter top-k ; softmax(64)
// Round 15: round-11 GEMM (best: 69.2us) + deterministic fixed-point atomic
// epilogue. Consumers atomicAdd Q32 (acc * 2^32, int64) into a 32KB global
// accumulator -> kills the 7.3MB partials round-trip and one kernel launch.
// Integer atomics are order-independent => deterministic. Finalize (64x64)
// converts, adds bias, top-k ranks, softmax, and re-zeroes the accumulator
// so every graph replay starts from zero.

#define K_TOTAL     786432
#define NBLK        444
#define TILE_K      64
#define TILES_TOTAL (K_TOTAL / TILE_K)        // 12288
#define BASE_T      (TILES_TOTAL / NBLK)      // 27
#define EXTRA_T     (TILES_TOTAL % NBLK)      // 300

#define NSTAGE 2
#define XH_OFF 0
#define XL_OFF 8192
#define WH_OFF 16384
#define WL_OFF 24576
#define BUF_BYTES 32768

#define BAR_FULL  1
#define BAR_EMPTY 3

#define Q32F 4294967296.0f     // 2^32
#define Q32I (1.0 / 4294967296.0)

__device__ unsigned long long g_acc[64 * 64];   // zero-init at module load

// ---------------- helpers ----------------

__device__ __forceinline__ uint32_t smem_u32(const void* p) {
    return (uint32_t)__cvta_generic_to_shared(p);
}

__device__ __forceinline__ void bar_sync(int id) {
    asm volatile("bar.sync %0, 256;" :: "r"(id) : "memory");
}
__device__ __forceinline__ void bar_arrive(int id) {
    asm volatile("bar.arrive %0, 256;" :: "r"(id) : "memory");
}

__device__ __forceinline__ void ldsm4(uint32_t* r, uint32_t addr) {
    asm volatile("ldmatrix.sync.aligned.m8n8.x4.shared.b16 {%0,%1,%2,%3}, [%4];"
                 : "=r"(r[0]), "=r"(r[1]), "=r"(r[2]), "=r"(r[3]) : "r"(addr));
}

__device__ __forceinline__ void mma16816(float* c, const uint32_t* a,
                                         uint32_t b0, uint32_t b1) {
    asm volatile(
        "mma.sync.aligned.m16n8k16.row.col.f32.bf16.bf16.f32 "
        "{%0,%1,%2,%3}, {%4,%5,%6,%7}, {%8,%9}, {%0,%1,%2,%3};"
        : "+f"(c[0]), "+f"(c[1]), "+f"(c[2]), "+f"(c[3])
        : "r"(a[0]), "r"(a[1]), "r"(a[2]), "r"(a[3]), "r"(b0), "r"(b1));
}

__device__ __forceinline__ void split4(float4 v, uint2& hi, uint2& lo) {
    __nv_bfloat162 h0 = __float22bfloat162_rn(make_float2(v.x, v.y));
    __nv_bfloat162 h1 = __float22bfloat162_rn(make_float2(v.z, v.w));
    float2 f0 = __bfloat1622float2(h0);
    float2 f1 = __bfloat1622float2(h1);
    __nv_bfloat162 l0 = __float22bfloat162_rn(make_float2(v.x - f0.x, v.y - f0.y));
    __nv_bfloat162 l1 = __float22bfloat162_rn(make_float2(v.z - f1.x, v.w - f1.y));
    hi.x = *(uint32_t*)&h0;  hi.y = *(uint32_t*)&h1;
    lo.x = *(uint32_t*)&l0;  lo.y = *(uint32_t*)&l1;
}

__device__ __forceinline__ uint32_t sw128(uint32_t off) {
    return off ^ ((off >> 3) & 0x70);
}

__device__ __forceinline__ void atom_q32(int idx, float v) {
    const long long q = __float2ll_rn(v * Q32F);
    atomicAdd(&g_acc[idx], (unsigned long long)q);
}

// ---------------- GEMM kernel (round-11 engine) ----------------

extern __shared__ char dsmem[];

__global__ __launch_bounds__(256, 3) void gemm_ws_kernel(
    const float* __restrict__ x, const float* __restrict__ W) {
    const int tid  = threadIdx.x;
    const int wid  = tid >> 5;
    const int lane = tid & 31;
    const int bid  = blockIdx.x;

    const int t0  = BASE_T * bid + (bid < EXTRA_T ? bid : EXTRA_T);
    const int cnt = BASE_T + (bid < EXTRA_T ? 1 : 0);
    const long kbase = (long)t0 * TILE_K;

    if (wid < 4) {
        // ================= PRODUCER: 128 threads =================
        const int q  = tid & 15;
        const int rb = tid >> 4;
        const float* xp = x + (long)rb * K_TOTAL + kbase + q * 4;
        const float* wp = W + (long)rb * K_TOTAL + kbase + q * 4;
        const long rstep = 8L * K_TOTAL;

        uint32_t soff[8];
#pragma unroll
        for (int i = 0; i < 8; ++i)
            soff[i] = sw128((uint32_t)((rb + 8 * i) * 128 + q * 8));

        int b = 0;
        for (int t = 0; t < cnt; ++t) {
            if (t >= NSTAGE) bar_sync(BAR_EMPTY + b);
            char* buf = dsmem + b * BUF_BYTES;
            const long koff = (long)t * TILE_K;

#pragma unroll
            for (int c = 0; c < 2; ++c) {          // x in two 4-row chunks
                float4 v[4];
#pragma unroll
                for (int i = 0; i < 4; ++i)
                    v[i] = *(const float4*)(xp + (c * 4 + i) * rstep + koff);
#pragma unroll
                for (int i = 0; i < 4; ++i) {
                    uint2 hi, lo;
                    split4(v[i], hi, lo);
                    *(uint2*)(buf + XH_OFF + soff[c * 4 + i]) = hi;
                    *(uint2*)(buf + XL_OFF + soff[c * 4 + i]) = lo;
                }
            }
#pragma unroll
            for (int c = 0; c < 2; ++c) {          // w in two 4-row chunks
                float4 v[4];
#pragma unroll
                for (int i = 0; i < 4; ++i)
                    v[i] = *(const float4*)(wp + (c * 4 + i) * rstep + koff);
#pragma unroll
                for (int i = 0; i < 4; ++i) {
                    uint2 hi, lo;
                    split4(v[i], hi, lo);
                    *(uint2*)(buf + WH_OFF + soff[c * 4 + i]) = hi;
                    *(uint2*)(buf + WL_OFF + soff[c * 4 + i]) = lo;
                }
            }

            bar_arrive(BAR_FULL + b);
            b ^= 1;
        }
    } else {
        // ================= CONSUMER: 4 warps, 32x32 quadrants =================
        const int cwid = wid - 4;
        const int wr = cwid >> 1;
        const int wc = cwid & 1;
        const int r0 = wr * 32;
        const int c0 = wc * 32;

        const uint32_t s0 = smem_u32(dsmem);
        const int arow0 = r0 + (lane & 15);
        const int bcol0 = c0 + (lane & 15);
        const uint32_t axm   = (uint32_t)((arow0 & 7) * 16);
        const uint32_t bxm   = (uint32_t)((bcol0 & 7) * 16);
        const uint32_t khalf = (uint32_t)((lane >> 4) * 16);

        const uint32_t aoff0 = (uint32_t)(arow0 * 128);
        const uint32_t aoff1 = (uint32_t)((arow0 + 16) * 128);
        const uint32_t boff0 = (uint32_t)(bcol0 * 128);
        const uint32_t boff1 = (uint32_t)((bcol0 + 16) * 128);

        float acc[2][4][4];
#pragma unroll
        for (int m = 0; m < 2; ++m)
#pragma unroll
            for (int n = 0; n < 4; ++n)
#pragma unroll
                for (int f = 0; f < 4; ++f) acc[m][n][f] = 0.0f;

        int b = 0;
        for (int t = 0; t < cnt; ++t) {
            bar_sync(BAR_FULL + b);
            const uint32_t sb = s0 + (uint32_t)b * BUF_BYTES;

#pragma unroll
            for (int ks = 0; ks < 4; ++ks) {
                const uint32_t kterm = (uint32_t)(ks * 32) + khalf;
                const uint32_t ka = kterm ^ axm;
                const uint32_t kb = kterm ^ bxm;

                uint32_t ah0[4], ah1[4], bha[4], bhb[4];
                ldsm4(ah0, sb + XH_OFF + aoff0 + ka);
                ldsm4(ah1, sb + XH_OFF + aoff1 + ka);
                ldsm4(bha, sb + WH_OFF + boff0 + kb);
                ldsm4(bhb, sb + WH_OFF + boff1 + kb);
                // hh
                mma16816(acc[0][0], ah0, bha[0], bha[2]);
                mma16816(acc[0][1], ah0, bha[1], bha[3]);
                mma16816(acc[0][2], ah0, bhb[0], bhb[2]);
                mma16816(acc[0][3], ah0, bhb[1], bhb[3]);
                mma16816(acc[1][0], ah1, bha[0], bha[2]);
                mma16816(acc[1][1], ah1, bha[1], bha[3]);
                mma16816(acc[1][2], ah1, bhb[0], bhb[2]);
                mma16816(acc[1][3], ah1, bhb[1], bhb[3]);
                {   // hl: reuse ah, load wl frags
                    uint32_t bla[4], blb[4];
                    ldsm4(bla, sb + WL_OFF + boff0 + kb);
                    ldsm4(blb, sb + WL_OFF + boff1 + kb);
                    mma16816(acc[0][0], ah0, bla[0], bla[2]);
                    mma16816(acc[0][1], ah0, bla[1], bla[3]);
                    mma16816(acc[0][2], ah0, blb[0], blb[2]);
                    mma16816(acc[0][3], ah0, blb[1], blb[3]);
                    mma16816(acc[1][0], ah1, bla[0], bla[2]);
                    mma16816(acc[1][1], ah1, bla[1], bla[3]);
                    mma16816(acc[1][2], ah1, blb[0], blb[2]);
                    mma16816(acc[1][3], ah1, blb[1], blb[3]);
                }
                {   // lh: load xl frags, reuse bh
                    uint32_t al0[4], al1[4];
                    ldsm4(al0, sb + XL_OFF + aoff0 + ka);
                    ldsm4(al1, sb + XL_OFF + aoff1 + ka);
                    mma16816(acc[0][0], al0, bha[0], bha[2]);
                    mma16816(acc[0][1], al0, bha[1], bha[3]);
                    mma16816(acc[0][2], al0, bhb[0], bhb[2]);
                    mma16816(acc[0][3], al0, bhb[1], bhb[3]);
                    mma16816(acc[1][0], al1, bha[0], bha[2]);
                    mma16816(acc[1][1], al1, bha[1], bha[3]);
                    mma16816(acc[1][2], al1, bhb[0], bhb[2]);
                    mma16816(acc[1][3], al1, bhb[1], bhb[3]);
                }
            }

            bar_arrive(BAR_EMPTY + b);
            b ^= 1;
        }

        // epilogue: deterministic Q32 fixed-point atomic accumulation
        const int gr = lane >> 2;
        const int gc = (lane & 3) * 2;
#pragma unroll
        for (int m = 0; m < 2; ++m)
#pragma unroll
            for (int n = 0; n < 4; ++n) {
                const int rr = r0 + m * 16 + gr;
                const int cc = c0 + n * 8 + gc;
                atom_q32(rr * 64 + cc,           acc[m][n][0]);
                atom_q32(rr * 64 + cc + 1,       acc[m][n][1]);
                atom_q32((rr + 8) * 64 + cc,     acc[m][n][2]);
                atom_q32((rr + 8) * 64 + cc + 1, acc[m][n][3]);
            }
    }
}

// ---------------- finalize: convert + bias + top-k + softmax + re-zero --------

__global__ __launch_bounds__(64) void finalize_kernel(
    const float* __restrict__ bias, const int* __restrict__ kp,
    float* __restrict__ out) {
    const int b = blockIdx.x;       // batch row, 64 blocks
    const int e = threadIdx.x;      // expert, 64 threads

    __shared__ float ys[64];
    __shared__ float evs[64];

    const long long q = (long long)g_acc[b * 64 + e];
    g_acc[b * 64 + e] = 0ULL;       // re-zero for the next replay
    const float yv = (float)((double)q * Q32I) + bias[e];
    ys[e] = yv;
    __syncthreads();

    const int kk = *kp;
    int rank = 0;
#pragma unroll 8
    for (int j = 0; j < 64; ++j) {
        const float yj = ys[j];
        rank += (yj > yv) || (yj == yv && j < e);
    }
    const float ev = (rank < kk) ? expf(yv) : 1.0f;
    evs[e] = ev;
    __syncthreads();

    for (int off = 32; off > 0; off >>= 1) {
        if (e < off) evs[e] += evs[e + off];
        __syncthreads();
    }
    out[b * 64 + e] = ev / evs[0];
}

extern "C" void kernel_launch(void* const* d_in, const int* in_sizes, int n_in,
                              void* d_out, int out_size) {
    const float* x    = (const float*)d_in[0];
    const float* W    = (const float*)d_in[1];
    const float* bias = (const float*)d_in[2];
    const int*   kp   = (const int*)d_in[3];
    float* out = (float*)d_out;

    cudaFuncSetAttribute(gemm_ws_kernel,
                         cudaFuncAttributeMaxDynamicSharedMemorySize,
                         NSTAGE * BUF_BYTES);
    gemm_ws_kernel<<<NBLK, 256, NSTAGE * BUF_BYTES>>>(x, W);
    finalize_kernel<<<64, 64>>>(bias, kp, out);
}

// round 16
// speedup vs baseline: 1.0858x; 1.0858x over previous
#include <cuda_runtime.h>
#include <cuda_bf16.h>
#include <cstdint>

// TopKRoute: y = x.reshape(64, 786432) @ W^T + b ; scatter top-k ; softmax(64)
// Round 16: round-11 GEMM (proven 69.2us) + SLOTTED deterministic Q32 atomic
// epilogue. 16 accumulator slots (CTA bid & 15) cut per-address atomic
// contention 444 -> <=28, removing the +6us drain seen with a single buffer.
// Finalize (64x256) sums 16 slots, converts, bias+topk+softmax, re-zeroes.

#define K_TOTAL     786432
#define NBLK        444
#define TILE_K      64
#define TILES_TOTAL (K_TOTAL / TILE_K)        // 12288
#define BASE_T      (TILES_TOTAL / NBLK)      // 27
#define EXTRA_T     (TILES_TOTAL % NBLK)      // 300

#define NSTAGE 2
#define XH_OFF 0
#define XL_OFF 8192
#define WH_OFF 16384
#define WL_OFF 24576
#define BUF_BYTES 32768

#define BAR_FULL  1
#define BAR_EMPTY 3

#define NSLOT 16
#define Q32F 4294967296.0f     // 2^32
#define Q32I (1.0 / 4294967296.0)

__device__ unsigned long long g_acc[NSLOT][64 * 64];   // zero-init at load

// ---------------- helpers ----------------

__device__ __forceinline__ uint32_t smem_u32(const void* p) {
    return (uint32_t)__cvta_generic_to_shared(p);
}

__device__ __forceinline__ void bar_sync(int id) {
    asm volatile("bar.sync %0, 256;" :: "r"(id) : "memory");
}
__device__ __forceinline__ void bar_arrive(int id) {
    asm volatile("bar.arrive %0, 256;" :: "r"(id) : "memory");
}

__device__ __forceinline__ void ldsm4(uint32_t* r, uint32_t addr) {
    asm volatile("ldmatrix.sync.aligned.m8n8.x4.shared.b16 {%0,%1,%2,%3}, [%4];"
                 : "=r"(r[0]), "=r"(r[1]), "=r"(r[2]), "=r"(r[3]) : "r"(addr));
}

__device__ __forceinline__ void mma16816(float* c, const uint32_t* a,
                                         uint32_t b0, uint32_t b1) {
    asm volatile(
        "mma.sync.aligned.m16n8k16.row.col.f32.bf16.bf16.f32 "
        "{%0,%1,%2,%3}, {%4,%5,%6,%7}, {%8,%9}, {%0,%1,%2,%3};"
        : "+f"(c[0]), "+f"(c[1]), "+f"(c[2]), "+f"(c[3])
        : "r"(a[0]), "r"(a[1]), "r"(a[2]), "r"(a[3]), "r"(b0), "r"(b1));
}

__device__ __forceinline__ void split4(float4 v, uint2& hi, uint2& lo) {
    __nv_bfloat162 h0 = __float22bfloat162_rn(make_float2(v.x, v.y));
    __nv_bfloat162 h1 = __float22bfloat162_rn(make_float2(v.z, v.w));
    float2 f0 = __bfloat1622float2(h0);
    float2 f1 = __bfloat1622float2(h1);
    __nv_bfloat162 l0 = __float22bfloat162_rn(make_float2(v.x - f0.x, v.y - f0.y));
    __nv_bfloat162 l1 = __float22bfloat162_rn(make_float2(v.z - f1.x, v.w - f1.y));
    hi.x = *(uint32_t*)&h0;  hi.y = *(uint32_t*)&h1;
    lo.x = *(uint32_t*)&l0;  lo.y = *(uint32_t*)&l1;
}

__device__ __forceinline__ uint32_t sw128(uint32_t off) {
    return off ^ ((off >> 3) & 0x70);
}

// ---------------- GEMM kernel (round-11 engine) ----------------

extern __shared__ char dsmem[];

__global__ __launch_bounds__(256, 3) void gemm_ws_kernel(
    const float* __restrict__ x, const float* __restrict__ W) {
    const int tid  = threadIdx.x;
    const int wid  = tid >> 5;
    const int lane = tid & 31;
    const int bid  = blockIdx.x;

    const int t0  = BASE_T * bid + (bid < EXTRA_T ? bid : EXTRA_T);
    const int cnt = BASE_T + (bid < EXTRA_T ? 1 : 0);
    const long kbase = (long)t0 * TILE_K;

    if (wid < 4) {
        // ================= PRODUCER: 128 threads =================
        const int q  = tid & 15;
        const int rb = tid >> 4;
        const float* xp = x + (long)rb * K_TOTAL + kbase + q * 4;
        const float* wp = W + (long)rb * K_TOTAL + kbase + q * 4;
        const long rstep = 8L * K_TOTAL;

        uint32_t soff[8];
#pragma unroll
        for (int i = 0; i < 8; ++i)
            soff[i] = sw128((uint32_t)((rb + 8 * i) * 128 + q * 8));

        int b = 0;
        for (int t = 0; t < cnt; ++t) {
            if (t >= NSTAGE) bar_sync(BAR_EMPTY + b);
            char* buf = dsmem + b * BUF_BYTES;
            const long koff = (long)t * TILE_K;

#pragma unroll
            for (int c = 0; c < 2; ++c) {          // x in two 4-row chunks
                float4 v[4];
#pragma unroll
                for (int i = 0; i < 4; ++i)
                    v[i] = *(const float4*)(xp + (c * 4 + i) * rstep + koff);
#pragma unroll
                for (int i = 0; i < 4; ++i) {
                    uint2 hi, lo;
                    split4(v[i], hi, lo);
                    *(uint2*)(buf + XH_OFF + soff[c * 4 + i]) = hi;
                    *(uint2*)(buf + XL_OFF + soff[c * 4 + i]) = lo;
                }
            }
#pragma unroll
            for (int c = 0; c < 2; ++c) {          // w in two 4-row chunks
                float4 v[4];
#pragma unroll
                for (int i = 0; i < 4; ++i)
                    v[i] = *(const float4*)(wp + (c * 4 + i) * rstep + koff);
#pragma unroll
                for (int i = 0; i < 4; ++i) {
                    uint2 hi, lo;
                    split4(v[i], hi, lo);
                    *(uint2*)(buf + WH_OFF + soff[c * 4 + i]) = hi;
                    *(uint2*)(buf + WL_OFF + soff[c * 4 + i]) = lo;
                }
            }

            bar_arrive(BAR_FULL + b);
            b ^= 1;
        }
    } else {
        // ================= CONSUMER: 4 warps, 32x32 quadrants =================
        const int cwid = wid - 4;
        const int wr = cwid >> 1;
        const int wc = cwid & 1;
        const int r0 = wr * 32;
        const int c0 = wc * 32;

        const uint32_t s0 = smem_u32(dsmem);
        const int arow0 = r0 + (lane & 15);
        const int bcol0 = c0 + (lane & 15);
        const uint32_t axm   = (uint32_t)((arow0 & 7) * 16);
        const uint32_t bxm   = (uint32_t)((bcol0 & 7) * 16);
        const uint32_t khalf = (uint32_t)((lane >> 4) * 16);

        const uint32_t aoff0 = (uint32_t)(arow0 * 128);
        const uint32_t aoff1 = (uint32_t)((arow0 + 16) * 128);
        const uint32_t boff0 = (uint32_t)(bcol0 * 128);
        const uint32_t boff1 = (uint32_t)((bcol0 + 16) * 128);

        float acc[2][4][4];
#pragma unroll
        for (int m = 0; m < 2; ++m)
#pragma unroll
            for (int n = 0; n < 4; ++n)
#pragma unroll
                for (int f = 0; f < 4; ++f) acc[m][n][f] = 0.0f;

        int b = 0;
        for (int t = 0; t < cnt; ++t) {
            bar_sync(BAR_FULL + b);
            const uint32_t sb = s0 + (uint32_t)b * BUF_BYTES;

#pragma unroll
            for (int ks = 0; ks < 4; ++ks) {
                const uint32_t kterm = (uint32_t)(ks * 32) + khalf;
                const uint32_t ka = kterm ^ axm;
                const uint32_t kb = kterm ^ bxm;

                uint32_t ah0[4], ah1[4], bha[4], bhb[4];
                ldsm4(ah0, sb + XH_OFF + aoff0 + ka);
                ldsm4(ah1, sb + XH_OFF + aoff1 + ka);
                ldsm4(bha, sb + WH_OFF + boff0 + kb);
                ldsm4(bhb, sb + WH_OFF + boff1 + kb);
                // hh
                mma16816(acc[0][0], ah0, bha[0], bha[2]);
                mma16816(acc[0][1], ah0, bha[1], bha[3]);
                mma16816(acc[0][2], ah0, bhb[0], bhb[2]);
                mma16816(acc[0][3], ah0, bhb[1], bhb[3]);
                mma16816(acc[1][0], ah1, bha[0], bha[2]);
                mma16816(acc[1][1], ah1, bha[1], bha[3]);
                mma16816(acc[1][2], ah1, bhb[0], bhb[2]);
                mma16816(acc[1][3], ah1, bhb[1], bhb[3]);
                {   // hl: reuse ah, load wl frags
                    uint32_t bla[4], blb[4];
                    ldsm4(bla, sb + WL_OFF + boff0 + kb);
                    ldsm4(blb, sb + WL_OFF + boff1 + kb);
                    mma16816(acc[0][0], ah0, bla[0], bla[2]);
                    mma16816(acc[0][1], ah0, bla[1], bla[3]);
                    mma16816(acc[0][2], ah0, blb[0], blb[2]);
                    mma16816(acc[0][3], ah0, blb[1], blb[3]);
                    mma16816(acc[1][0], ah1, bla[0], bla[2]);
                    mma16816(acc[1][1], ah1, bla[1], bla[3]);
                    mma16816(acc[1][2], ah1, blb[0], blb[2]);
                    mma16816(acc[1][3], ah1, blb[1], blb[3]);
                }
                {   // lh: load xl frags, reuse bh
                    uint32_t al0[4], al1[4];
                    ldsm4(al0, sb + XL_OFF + aoff0 + ka);
                    ldsm4(al1, sb + XL_OFF + aoff1 + ka);
                    mma16816(acc[0][0], al0, bha[0], bha[2]);
                    mma16816(acc[0][1], al0, bha[1], bha[3]);
                    mma16816(acc[0][2], al0, bhb[0], bhb[2]);
                    mma16816(acc[0][3], al0, bhb[1], bhb[3]);
                    mma16816(acc[1][0], al1, bha[0], bha[2]);
                    mma16816(acc[1][1], al1, bha[1], bha[3]);
                    mma16816(acc[1][2], al1, bhb[0], bhb[2]);
                    mma16816(acc[1][3], al1, bhb[1], bhb[3]);
                }
            }

            bar_arrive(BAR_EMPTY + b);
            b ^= 1;
        }

        // epilogue: deterministic slotted Q32 atomic accumulation
        unsigned long long* slot = g_acc[bid & (NSLOT - 1)];
        const int gr = lane >> 2;
        const int gc = (lane & 3) * 2;
#pragma unroll
        for (int m = 0; m < 2; ++m)
#pragma unroll
            for (int n = 0; n < 4; ++n) {
                const int rr = r0 + m * 16 + gr;
                const int cc = c0 + n * 8 + gc;
                atomicAdd(&slot[rr * 64 + cc],
                          (unsigned long long)__float2ll_rn(acc[m][n][0] * Q32F));
                atomicAdd(&slot[rr * 64 + cc + 1],
                          (unsigned long long)__float2ll_rn(acc[m][n][1] * Q32F));
                atomicAdd(&slot[(rr + 8) * 64 + cc],
                          (unsigned long long)__float2ll_rn(acc[m][n][2] * Q32F));
                atomicAdd(&slot[(rr + 8) * 64 + cc + 1],
                          (unsigned long long)__float2ll_rn(acc[m][n][3] * Q32F));
            }
    }
}

// ------- finalize: sum 16 slots + bias + top-k + softmax + re-zero -------

__global__ __launch_bounds__(256) void finalize_kernel(
    const float* __restrict__ bias, const int* __restrict__ kp,
    float* __restrict__ out) {
    const int b = blockIdx.x;       // batch row, 64 blocks
    const int t = threadIdx.x;      // 256 threads
    const int e = t & 63;           // expert
    const int p = t >> 6;           // 0..3 (4 slots each)

    long long sum = 0;
#pragma unroll
    for (int s = 0; s < 4; ++s) {
        const int si = p * 4 + s;
        sum += (long long)g_acc[si][b * 64 + e];
        g_acc[si][b * 64 + e] = 0ULL;   // re-zero for next replay
    }

    __shared__ long long accq[4][64];
    __shared__ float ys[64];
    __shared__ float evs[64];

    accq[p][e] = sum;
    __syncthreads();
    if (p == 0) {
        const long long q = accq[0][e] + accq[1][e] + accq[2][e] + accq[3][e];
        ys[e] = (float)((double)q * Q32I) + bias[e];
    }
    __syncthreads();

    const float yv = ys[e];
    const int kk = *kp;
    int rank = 0;
#pragma unroll 8
    for (int j = 0; j < 64; ++j) {
        const float yj = ys[j];
        rank += (yj > yv) || (yj == yv && j < e);
    }
    const float ev = (rank < kk) ? expf(yv) : 1.0f;
    if (p == 0) evs[e] = ev;
    __syncthreads();

    for (int off = 32; off > 0; off >>= 1) {
        if (t < off) evs[t] += evs[t + off];
        __syncthreads();
    }
    const float denom = evs[0];

    if (p == 0) out[b * 64 + e] = ev / denom;
}

extern "C" void kernel_launch(void* const* d_in, const int* in_sizes, int n_in,
                              void* d_out, int out_size) {
    const float* x    = (const float*)d_in[0];
    const float* W    = (const float*)d_in[1];
    const float* bias = (const float*)d_in[2];
    const int*   kp   = (const int*)d_in[3];
    float* out = (float*)d_out;

    cudaFuncSetAttribute(gemm_ws_kernel,
                         cudaFuncAttributeMaxDynamicSharedMemorySize,
                         NSTAGE * BUF_BYTES);
    gemm_ws_kernel<<<NBLK, 256, NSTAGE * BUF_BYTES>>>(x, W);
    finalize_kernel<<<64, 256>>>(bias, kp, out);
}